// round 6
// baseline (speedup 1.0000x reference)
#include <cuda_runtime.h>
#include <math.h>

#define PP 32
#define VV 200
#define FF 5
#define TT 16
#define RR 5
#define GG 80
#define KK 16
#define BBATCH 16
#define NLL 7
#define EPSF 1e-5f
#define XROW 51200
#define BIGLEN 32000
#define LOG2E 1.44269504088896340736f

// scratch
__device__ float g_h[BBATCH * PP * GG];        // h activations (B,P,G)
__device__ float g_p2[BBATCH * 8 * 64];        // W2 partial sums (B, slice, 64)

// ---- packed fp32x2 helpers (Blackwell FFMA2 path) ----
__device__ __forceinline__ unsigned long long pk2(float a, float b) {
    unsigned long long r;
    asm("mov.b64 %0, {%1,%2};" : "=l"(r) : "f"(a), "f"(b));
    return r;
}
__device__ __forceinline__ void f2fma(unsigned long long& d, unsigned long long a,
                                      unsigned long long b) {
    asm("fma.rn.f32x2 %0, %1, %2, %0;" : "+l"(d) : "l"(a), "l"(b));
}
__device__ __forceinline__ unsigned long long f2mul(unsigned long long a,
                                                    unsigned long long b) {
    unsigned long long r;
    asm("mul.rn.f32x2 %0, %1, %2;" : "=l"(r) : "l"(a), "l"(b));
    return r;
}
__device__ __forceinline__ float f2sum(unsigned long long a) {
    float x, y;
    asm("mov.b64 {%0,%1}, %2;" : "=f"(x), "=f"(y) : "l"(a));
    return x + y;
}
__device__ __forceinline__ float ex2f(float x) {
    float y;
    asm("ex2.approx.f32 %0, %1;" : "=f"(y) : "f"(x));
    return y;
}
__device__ __forceinline__ unsigned long long lds2(const float* p) {
    return *(const unsigned long long*)p;   // 8B-aligned by construction
}

// ---------------------------------------------------------------------------
// Kernel 1: one CTA per (b,p). desc -> conv(max over K rotations) -> W1 -> g_h
// Phase B split into two r-passes to cut registers below 85 -> 3 CTAs/SM.
// ---------------------------------------------------------------------------
__global__ void __launch_bounds__(256, 3)
masif_k1(const float* __restrict__ x,
         const float* __restrict__ mu_rho,
         const float* __restrict__ sigma_rho,
         const float* __restrict__ mu_theta,
         const float* __restrict__ sigma_theta,
         const float* __restrict__ W_conv,
         const float* __restrict__ b_conv,
         const float* __restrict__ W1,
         const float* __restrict__ b1)
{
    __shared__ float s_th[VV];            // raw theta
    __shared__ float s_c[RR][VV];         // rho gaussians * mask
    __shared__ float s_feat[FF][VV];      // transposed features
    __shared__ float s_mut[TT];
    __shared__ float s_invt[TT];          // LOG2E / (sigma_t^2 + eps)
    __shared__ float s_desc[KK][FF * GG]; // desc[k][f*80+g]
    __shared__ float s_conv[FF * GG];
    __shared__ float s_pmax[3][FF * GG];
    __shared__ float s_hp[3][GG];

    const int tid = threadIdx.x;
    const int bp  = blockIdx.x;
    const int b   = bp / PP;
    const int p   = bp % PP;

    const float* xb    = x + (size_t)b * XROW;
    const float* rhop  = xb + BIGLEN + 0 * PP * VV + p * VV;
    const float* thp   = xb + BIGLEN + 1 * PP * VV + p * VV;
    const float* maskp = xb + BIGLEN + 2 * PP * VV + p * VV;
    const float* featp = xb + p * VV * FF;

    const float TWO_PI = 6.28318530717958647692f;
    const float OFF_STEP = (float)(2.0 * M_PI / 16.0);

    if (tid < TT) {
        s_mut[tid] = mu_theta[tid];
        float st = sigma_theta[tid];
        s_invt[tid] = LOG2E / (st * st + EPSF);
    }

    // Phase A: rho gaussians, feature transpose, theta copy
    if (tid < VV) {
        int v = tid;
        float rv = rhop[v];
        float mv = maskp[v];
        s_th[v] = thp[v];
#pragma unroll
        for (int f = 0; f < FF; ++f)
            s_feat[f][v] = featp[v * FF + f];
#pragma unroll
        for (int r = 0; r < RR; ++r) {
            float mr = mu_rho[r * TT];      // depends only on r
            float sr = sigma_rho[r * TT];
            float d = rv - mr;
            float c = ex2f(-(d * d) * (LOG2E / (sr * sr + EPSF))) * mv;
            s_c[r][v] = c;
        }
    }
    __syncthreads();

    // Phase B: per thread (k,t), two passes over r to limit live registers.
    {
        const int k = tid >> 4;
        const int t = tid & 15;
        const float mut  = s_mut[t];
        const float invt = s_invt[t];
        const float offk = OFF_STEP * (float)k;

        // ---- pass 1: r = 0,1,2 ----
        {
            unsigned long long acc[3 * FF];
            unsigned long long accd[3];
#pragma unroll
            for (int i = 0; i < 3 * FF; ++i) acc[i] = 0ull;
#pragma unroll
            for (int r = 0; r < 3; ++r) accd[r] = 0ull;

            for (int v = 0; v < VV; v += 2) {
                float2 th2 = *(const float2*)(s_th + v);
                float u0 = th2.x + offk; if (u0 >= TWO_PI) u0 -= TWO_PI;
                float u1 = th2.y + offk; if (u1 >= TWO_PI) u1 -= TWO_PI;
                float d0 = u0 - mut, d1 = u1 - mut;
                float a0 = ex2f(-(d0 * d0) * invt);
                float a1 = ex2f(-(d1 * d1) * invt);
                unsigned long long A = pk2(a0, a1);

                unsigned long long Fv[FF];
#pragma unroll
                for (int f = 0; f < FF; ++f) Fv[f] = lds2(&s_feat[f][v]);

#pragma unroll
                for (int r = 0; r < 3; ++r) {
                    unsigned long long C = lds2(&s_c[r][v]);
                    f2fma(accd[r], A, C);
                    unsigned long long Q = f2mul(A, C);
#pragma unroll
                    for (int f = 0; f < FF; ++f)
                        f2fma(acc[r * FF + f], Q, Fv[f]);
                }
            }
#pragma unroll
            for (int r = 0; r < 3; ++r) {
                float inv = 1.0f / (f2sum(accd[r]) + EPSF);
#pragma unroll
                for (int f = 0; f < FF; ++f)
                    s_desc[k][f * GG + r * TT + t] = f2sum(acc[r * FF + f]) * inv;
            }
        }

        // ---- pass 2: r = 3,4 ----
        {
            unsigned long long acc[2 * FF];
            unsigned long long accd[2];
#pragma unroll
            for (int i = 0; i < 2 * FF; ++i) acc[i] = 0ull;
#pragma unroll
            for (int r = 0; r < 2; ++r) accd[r] = 0ull;

            for (int v = 0; v < VV; v += 2) {
                float2 th2 = *(const float2*)(s_th + v);
                float u0 = th2.x + offk; if (u0 >= TWO_PI) u0 -= TWO_PI;
                float u1 = th2.y + offk; if (u1 >= TWO_PI) u1 -= TWO_PI;
                float d0 = u0 - mut, d1 = u1 - mut;
                float a0 = ex2f(-(d0 * d0) * invt);
                float a1 = ex2f(-(d1 * d1) * invt);
                unsigned long long A = pk2(a0, a1);

                unsigned long long Fv[FF];
#pragma unroll
                for (int f = 0; f < FF; ++f) Fv[f] = lds2(&s_feat[f][v]);

#pragma unroll
                for (int r = 0; r < 2; ++r) {
                    unsigned long long C = lds2(&s_c[3 + r][v]);
                    f2fma(accd[r], A, C);
                    unsigned long long Q = f2mul(A, C);
#pragma unroll
                    for (int f = 0; f < FF; ++f)
                        f2fma(acc[r * FF + f], Q, Fv[f]);
                }
            }
#pragma unroll
            for (int r = 0; r < 2; ++r) {
                float inv = 1.0f / (f2sum(accd[r]) + EPSF);
#pragma unroll
                for (int f = 0; f < FF; ++f)
                    s_desc[k][f * GG + (3 + r) * TT + t] = f2sum(acc[r * FF + f]) * inv;
            }
        }
    }
    __syncthreads();

    // Phase C: conv(f,h) = max_k sum_g desc_k(f,g)*Wc(f,g,h)
    // g-loop unrolled x2 (step 4) so 4 independent LDGs are in flight.
    if (tid < 240) {
        const int h  = tid % GG;
        const int kg = tid / GG;           // 0,1,2 -> k ranges 0-5, 6-11, 12-15
        const int kbase = kg * 6;
        const int nk = (kg == 2) ? 4 : 6;
#pragma unroll 1
        for (int f = 0; f < FF; ++f) {
            unsigned long long a2[6];
#pragma unroll
            for (int j = 0; j < 6; ++j) a2[j] = 0ull;
            const float* Wf = W_conv + f * GG * GG + h;
            for (int g = 0; g < GG; g += 4) {
                float w0 = __ldg(Wf + (g + 0) * GG);
                float w1 = __ldg(Wf + (g + 1) * GG);
                float w2 = __ldg(Wf + (g + 2) * GG);
                float w3 = __ldg(Wf + (g + 3) * GG);
                unsigned long long Wp0 = pk2(w0, w1);
                unsigned long long Wp1 = pk2(w2, w3);
#pragma unroll
                for (int j = 0; j < 6; ++j) {
                    if (j < nk) {
                        unsigned long long Dp0 = lds2(&s_desc[kbase + j][f * GG + g]);
                        unsigned long long Dp1 = lds2(&s_desc[kbase + j][f * GG + g + 2]);
                        f2fma(a2[j], Dp0, Wp0);
                        f2fma(a2[j], Dp1, Wp1);
                    }
                }
            }
            float m = -INFINITY;
#pragma unroll
            for (int j = 0; j < 6; ++j)
                if (j < nk) m = fmaxf(m, f2sum(a2[j]));
            s_pmax[kg][f * GG + h] = m;
        }
    }
    __syncthreads();
    for (int i = tid; i < FF * GG; i += 256) {
        float m = fmaxf(fmaxf(s_pmax[0][i], s_pmax[1][i]), s_pmax[2][i]);
        s_conv[i] = fmaxf(m + b_conv[i], 0.0f);
    }
    __syncthreads();

    // Phase D: h(j) = relu(sum_i conv(i)*W1[i][j] + b1[j]); 2 indep chains
    if (tid < 240) {
        int j = tid % GG;
        int part = tid / GG;
        int i0 = part * 134;
        int i1 = (i0 + 134 < 400) ? (i0 + 134) : 400;
        float sa = 0.0f, sb = 0.0f;
        int i = i0;
        for (; i + 1 < i1; i += 2) {
            sa = fmaf(s_conv[i],     __ldg(W1 + (i)     * GG + j), sa);
            sb = fmaf(s_conv[i + 1], __ldg(W1 + (i + 1) * GG + j), sb);
        }
        if (i < i1) sa = fmaf(s_conv[i], __ldg(W1 + i * GG + j), sa);
        s_hp[part][j] = sa + sb;
    }
    __syncthreads();
    if (tid < GG) {
        float hv = s_hp[0][tid] + s_hp[1][tid] + s_hp[2][tid] + b1[tid];
        g_h[bp * GG + tid] = fmaxf(hv, 0.0f);
    }
}

// ---------------------------------------------------------------------------
// Kernel 2a: grid (slice s=0..7, batch b). cov slice (10 rows) + W2 partial.
// ---------------------------------------------------------------------------
__global__ void __launch_bounds__(256, 4)
masif_k2a(const float* __restrict__ W2)
{
    __shared__ float s_h[PP][GG];
    __shared__ float s_cov[800];
    __shared__ float s_red[4][64];

    const int tid = threadIdx.x;
    const int s = blockIdx.x;
    const int b = blockIdx.y;

    for (int i = tid; i < PP * GG; i += 256)
        s_h[i / GG][i % GG] = g_h[b * PP * GG + i];
    __syncthreads();

    for (int idx = tid; idx < 800; idx += 256) {
        int i1 = s * 10 + idx / GG;
        int i2 = idx % GG;
        float acc = 0.0f;
#pragma unroll
        for (int pp = 0; pp < PP; ++pp)
            acc = fmaf(s_h[pp][i1], s_h[pp][i2], acc);
        s_cov[idx] = acc * (1.0f / 32.0f);
    }
    __syncthreads();

    {
        const int j = tid % 64;
        const int part = tid / 64;
        const float* W2s = W2 + ((size_t)s * 800 + part * 200) * 64 + j;
        const float* cv = s_cov + part * 200;
        float a0 = 0.f, a1 = 0.f, a2 = 0.f, a3 = 0.f;
#pragma unroll 4
        for (int i = 0; i < 200; i += 4) {
            a0 = fmaf(cv[i + 0], __ldg(W2s + (size_t)(i + 0) * 64), a0);
            a1 = fmaf(cv[i + 1], __ldg(W2s + (size_t)(i + 1) * 64), a1);
            a2 = fmaf(cv[i + 2], __ldg(W2s + (size_t)(i + 2) * 64), a2);
            a3 = fmaf(cv[i + 3], __ldg(W2s + (size_t)(i + 3) * 64), a3);
        }
        s_red[part][j] = (a0 + a1) + (a2 + a3);
    }
    __syncthreads();
    if (tid < 64)
        g_p2[(b * 8 + s) * 64 + tid] =
            s_red[0][tid] + s_red[1][tid] + s_red[2][tid] + s_red[3][tid];
}

// ---------------------------------------------------------------------------
// Kernel 2b: one CTA per batch. reduce partials + relu + W3 + softmax.
// ---------------------------------------------------------------------------
__global__ void __launch_bounds__(64, 8)
masif_k2b(const float* __restrict__ b2,
          const float* __restrict__ W3, const float* __restrict__ b3,
          float* __restrict__ out)
{
    __shared__ float s_h2[64];
    __shared__ float s_logit[NLL];
    const int tid = threadIdx.x;
    const int b = blockIdx.x;

    {
        float v = b2[tid];
#pragma unroll
        for (int s = 0; s < 8; ++s)
            v += g_p2[(b * 8 + s) * 64 + tid];
        s_h2[tid] = fmaxf(v, 0.0f);
    }
    __syncthreads();
    if (tid < NLL) {
        float s = b3[tid];
#pragma unroll
        for (int j = 0; j < 64; ++j)
            s = fmaf(s_h2[j], W3[j * NLL + tid], s);
        s_logit[tid] = s;
    }
    __syncthreads();
    if (tid == 0) {
        float m = -INFINITY;
        for (int l = 0; l < NLL; ++l) m = fmaxf(m, s_logit[l]);
        float e[NLL];
        float sum = 0.0f;
        for (int l = 0; l < NLL; ++l) { e[l] = __expf(s_logit[l] - m); sum += e[l]; }
        float inv = 1.0f / sum;
        for (int l = 0; l < NLL; ++l) out[b * NLL + l] = e[l] * inv;
    }
}

extern "C" void kernel_launch(void* const* d_in, const int* in_sizes, int n_in,
                              void* d_out, int out_size)
{
    const float* x           = (const float*)d_in[0];
    const float* mu_rho      = (const float*)d_in[1];
    const float* sigma_rho   = (const float*)d_in[2];
    const float* mu_theta    = (const float*)d_in[3];
    const float* sigma_theta = (const float*)d_in[4];
    const float* W_conv      = (const float*)d_in[5];
    const float* b_conv      = (const float*)d_in[6];
    const float* W1          = (const float*)d_in[7];
    const float* b1          = (const float*)d_in[8];
    const float* W2          = (const float*)d_in[9];
    const float* b2          = (const float*)d_in[10];
    const float* W3          = (const float*)d_in[11];
    const float* b3          = (const float*)d_in[12];
    float* out = (float*)d_out;

    masif_k1<<<BBATCH * PP, 256>>>(x, mu_rho, sigma_rho, mu_theta, sigma_theta,
                                   W_conv, b_conv, W1, b1);
    masif_k2a<<<dim3(8, BBATCH), 256>>>(W2);
    masif_k2b<<<BBATCH, 64>>>(b2, W3, b3, out);
}

// round 7
// speedup vs baseline: 1.1802x; 1.1802x over previous
#include <cuda_runtime.h>
#include <math.h>

#define PP 32
#define VV 200
#define FF 5
#define TT 16
#define RR 5
#define GG 80
#define KK 16
#define BBATCH 16
#define NLL 7
#define EPSF 1e-5f
#define XROW 51200
#define BIGLEN 32000
#define LOG2E 1.44269504088896340736f

// scratch
__device__ float g_h[BBATCH * PP * GG];        // h activations (B,P,G)
__device__ float g_p2[BBATCH * 8 * 64];        // W2 partial sums (B, slice, 64)

// ---- packed fp32x2 helpers (Blackwell FFMA2 path) ----
__device__ __forceinline__ unsigned long long pk2(float a, float b) {
    unsigned long long r;
    asm("mov.b64 %0, {%1,%2};" : "=l"(r) : "f"(a), "f"(b));
    return r;
}
__device__ __forceinline__ void f2fma(unsigned long long& d, unsigned long long a,
                                      unsigned long long b) {
    asm("fma.rn.f32x2 %0, %1, %2, %0;" : "+l"(d) : "l"(a), "l"(b));
}
__device__ __forceinline__ unsigned long long f2mul(unsigned long long a,
                                                    unsigned long long b) {
    unsigned long long r;
    asm("mul.rn.f32x2 %0, %1, %2;" : "=l"(r) : "l"(a), "l"(b));
    return r;
}
__device__ __forceinline__ float f2sum(unsigned long long a) {
    float x, y;
    asm("mov.b64 {%0,%1}, %2;" : "=f"(x), "=f"(y) : "l"(a));
    return x + y;
}
__device__ __forceinline__ float ex2f(float x) {
    float y;
    asm("ex2.approx.f32 %0, %1;" : "=f"(y) : "f"(x));
    return y;
}
__device__ __forceinline__ unsigned long long lds2(const float* p) {
    return *(const unsigned long long*)p;   // 8B-aligned by construction
}

// ---------------------------------------------------------------------------
// Kernel 1: one CTA per (b,p). desc -> conv(max over K rotations) -> W1 -> g_h
// Phase B software-pipelined: exp of iter i+1 overlaps FMA block of iter i.
// ---------------------------------------------------------------------------
__global__ void __launch_bounds__(256, 2)
masif_k1(const float* __restrict__ x,
         const float* __restrict__ mu_rho,
         const float* __restrict__ sigma_rho,
         const float* __restrict__ mu_theta,
         const float* __restrict__ sigma_theta,
         const float* __restrict__ W_conv,
         const float* __restrict__ b_conv,
         const float* __restrict__ W1,
         const float* __restrict__ b1)
{
    __shared__ float s_th[VV];            // raw theta
    __shared__ float s_c[RR][VV];         // rho gaussians * mask
    __shared__ float s_feat[FF][VV];      // transposed features
    __shared__ float s_mut[TT];
    __shared__ float s_invt[TT];          // LOG2E / (sigma_t^2 + eps)
    __shared__ float s_desc[KK][FF * GG]; // desc[k][f*80+g]
    __shared__ float s_conv[FF * GG];
    __shared__ float s_pmax[3][FF * GG];
    __shared__ float s_hp[3][GG];

    const int tid = threadIdx.x;
    const int bp  = blockIdx.x;
    const int b   = bp / PP;
    const int p   = bp % PP;

    const float* xb    = x + (size_t)b * XROW;
    const float* rhop  = xb + BIGLEN + 0 * PP * VV + p * VV;
    const float* thp   = xb + BIGLEN + 1 * PP * VV + p * VV;
    const float* maskp = xb + BIGLEN + 2 * PP * VV + p * VV;
    const float* featp = xb + p * VV * FF;

    const float TWO_PI = 6.28318530717958647692f;
    const float OFF_STEP = (float)(2.0 * M_PI / 16.0);

    if (tid < TT) {
        s_mut[tid] = mu_theta[tid];
        float st = sigma_theta[tid];
        s_invt[tid] = LOG2E / (st * st + EPSF);
    }

    // Phase A: rho gaussians, feature transpose, theta copy
    if (tid < VV) {
        int v = tid;
        float rv = rhop[v];
        float mv = maskp[v];
        s_th[v] = thp[v];
#pragma unroll
        for (int f = 0; f < FF; ++f)
            s_feat[f][v] = featp[v * FF + f];
#pragma unroll
        for (int r = 0; r < RR; ++r) {
            float mr = mu_rho[r * TT];      // depends only on r
            float sr = sigma_rho[r * TT];
            float d = rv - mr;
            float c = ex2f(-(d * d) * (LOG2E / (sr * sr + EPSF))) * mv;
            s_c[r][v] = c;
        }
    }
    __syncthreads();

    // Phase B: per thread (k,t): D(row) = sum_v a(v) * c(r,v) * feat(f,v)
    // Pipelined: a(v+2) computed while FMA block of v issues.
    {
        const int k = tid >> 4;
        const int t = tid & 15;
        const float mut   = s_mut[t];
        const float nInvt = -s_invt[t];
        const float offk  = OFF_STEP * (float)k;

        unsigned long long acc[RR * FF];   // feat accumulators (pairs over v)
        unsigned long long accd[RR];       // denominator accumulators
#pragma unroll
        for (int i = 0; i < RR * FF; ++i) acc[i] = 0ull;
#pragma unroll
        for (int r = 0; r < RR; ++r) accd[r] = 0ull;

        auto body = [&](int v, unsigned long long A) {
            unsigned long long Fv[FF];
#pragma unroll
            for (int f = 0; f < FF; ++f) Fv[f] = lds2(&s_feat[f][v]);
#pragma unroll
            for (int r = 0; r < RR; ++r) {
                unsigned long long C = lds2(&s_c[r][v]);
                f2fma(accd[r], A, C);                  // denom += a*c
                unsigned long long Q = f2mul(A, C);
#pragma unroll
                for (int f = 0; f < FF; ++f)
                    f2fma(acc[r * FF + f], Q, Fv[f]);  // += (a*c)*feat
            }
        };

        // prologue: a-pair for v=0
        float a0, a1;
        {
            float2 th2 = *(const float2*)(s_th);
            float u0 = th2.x + offk; if (u0 >= TWO_PI) u0 -= TWO_PI;
            float u1 = th2.y + offk; if (u1 >= TWO_PI) u1 -= TWO_PI;
            float d0 = u0 - mut, d1 = u1 - mut;
            a0 = ex2f(d0 * d0 * nInvt);
            a1 = ex2f(d1 * d1 * nInvt);
        }

        for (int v = 0; v < VV - 2; v += 2) {
            unsigned long long A = pk2(a0, a1);
            // prefetch + compute next a-pair (independent of FMA block below)
            {
                float2 tn = *(const float2*)(s_th + v + 2);
                float u0 = tn.x + offk; if (u0 >= TWO_PI) u0 -= TWO_PI;
                float u1 = tn.y + offk; if (u1 >= TWO_PI) u1 -= TWO_PI;
                float d0 = u0 - mut, d1 = u1 - mut;
                a0 = ex2f(d0 * d0 * nInvt);
                a1 = ex2f(d1 * d1 * nInvt);
            }
            body(v, A);
        }
        // epilogue: last pair
        body(VV - 2, pk2(a0, a1));

#pragma unroll
        for (int r = 0; r < RR; ++r) {
            float inv = 1.0f / (f2sum(accd[r]) + EPSF);
#pragma unroll
            for (int f = 0; f < FF; ++f)
                s_desc[k][f * GG + r * TT + t] = f2sum(acc[r * FF + f]) * inv;
        }
    }
    __syncthreads();

    // Phase C: conv(f,h) = max_k sum_g desc_k(f,g)*Wc(f,g,h)
    // g-loop at step 8: 8 independent LDGs in flight vs L2 latency.
    if (tid < 240) {
        const int h  = tid % GG;
        const int kg = tid / GG;           // 0,1,2 -> k ranges 0-5, 6-11, 12-15
        const int kbase = kg * 6;
        const int nk = (kg == 2) ? 4 : 6;
#pragma unroll 1
        for (int f = 0; f < FF; ++f) {
            unsigned long long a2[6];
#pragma unroll
            for (int j = 0; j < 6; ++j) a2[j] = 0ull;
            const float* Wf = W_conv + f * GG * GG + h;
            for (int g = 0; g < GG; g += 8) {
                float w[8];
#pragma unroll
                for (int u = 0; u < 8; ++u)
                    w[u] = __ldg(Wf + (g + u) * GG);
                unsigned long long Wp0 = pk2(w[0], w[1]);
                unsigned long long Wp1 = pk2(w[2], w[3]);
                unsigned long long Wp2 = pk2(w[4], w[5]);
                unsigned long long Wp3 = pk2(w[6], w[7]);
#pragma unroll
                for (int j = 0; j < 6; ++j) {
                    if (j < nk) {
                        const float* dbase = &s_desc[kbase + j][f * GG + g];
                        f2fma(a2[j], lds2(dbase + 0), Wp0);
                        f2fma(a2[j], lds2(dbase + 2), Wp1);
                        f2fma(a2[j], lds2(dbase + 4), Wp2);
                        f2fma(a2[j], lds2(dbase + 6), Wp3);
                    }
                }
            }
            float m = -INFINITY;
#pragma unroll
            for (int j = 0; j < 6; ++j)
                if (j < nk) m = fmaxf(m, f2sum(a2[j]));
            s_pmax[kg][f * GG + h] = m;
        }
    }
    __syncthreads();
    for (int i = tid; i < FF * GG; i += 256) {
        float m = fmaxf(fmaxf(s_pmax[0][i], s_pmax[1][i]), s_pmax[2][i]);
        s_conv[i] = fmaxf(m + b_conv[i], 0.0f);
    }
    __syncthreads();

    // Phase D: h(j) = relu(sum_i conv(i)*W1[i][j] + b1[j]); 2 indep chains
    if (tid < 240) {
        int j = tid % GG;
        int part = tid / GG;
        int i0 = part * 134;
        int i1 = (i0 + 134 < 400) ? (i0 + 134) : 400;
        float sa = 0.0f, sb = 0.0f;
        int i = i0;
        for (; i + 1 < i1; i += 2) {
            sa = fmaf(s_conv[i],     __ldg(W1 + (i)     * GG + j), sa);
            sb = fmaf(s_conv[i + 1], __ldg(W1 + (i + 1) * GG + j), sb);
        }
        if (i < i1) sa = fmaf(s_conv[i], __ldg(W1 + i * GG + j), sa);
        s_hp[part][j] = sa + sb;
    }
    __syncthreads();
    if (tid < GG) {
        float hv = s_hp[0][tid] + s_hp[1][tid] + s_hp[2][tid] + b1[tid];
        g_h[bp * GG + tid] = fmaxf(hv, 0.0f);
    }
}

// ---------------------------------------------------------------------------
// Kernel 2a: grid (slice s=0..7, batch b). cov slice (10 rows) + W2 partial.
// ---------------------------------------------------------------------------
__global__ void __launch_bounds__(256, 4)
masif_k2a(const float* __restrict__ W2)
{
    __shared__ float s_h[PP][GG];
    __shared__ float s_cov[800];
    __shared__ float s_red[4][64];

    const int tid = threadIdx.x;
    const int s = blockIdx.x;
    const int b = blockIdx.y;

    for (int i = tid; i < PP * GG; i += 256)
        s_h[i / GG][i % GG] = g_h[b * PP * GG + i];
    __syncthreads();

    for (int idx = tid; idx < 800; idx += 256) {
        int i1 = s * 10 + idx / GG;
        int i2 = idx % GG;
        float acc = 0.0f;
#pragma unroll
        for (int pp = 0; pp < PP; ++pp)
            acc = fmaf(s_h[pp][i1], s_h[pp][i2], acc);
        s_cov[idx] = acc * (1.0f / 32.0f);
    }
    __syncthreads();

    {
        const int j = tid % 64;
        const int part = tid / 64;
        const float* W2s = W2 + ((size_t)s * 800 + part * 200) * 64 + j;
        const float* cv = s_cov + part * 200;
        float a0 = 0.f, a1 = 0.f, a2 = 0.f, a3 = 0.f;
#pragma unroll 4
        for (int i = 0; i < 200; i += 4) {
            a0 = fmaf(cv[i + 0], __ldg(W2s + (size_t)(i + 0) * 64), a0);
            a1 = fmaf(cv[i + 1], __ldg(W2s + (size_t)(i + 1) * 64), a1);
            a2 = fmaf(cv[i + 2], __ldg(W2s + (size_t)(i + 2) * 64), a2);
            a3 = fmaf(cv[i + 3], __ldg(W2s + (size_t)(i + 3) * 64), a3);
        }
        s_red[part][j] = (a0 + a1) + (a2 + a3);
    }
    __syncthreads();
    if (tid < 64)
        g_p2[(b * 8 + s) * 64 + tid] =
            s_red[0][tid] + s_red[1][tid] + s_red[2][tid] + s_red[3][tid];
}

// ---------------------------------------------------------------------------
// Kernel 2b: one CTA per batch. reduce partials + relu + W3 + softmax.
// ---------------------------------------------------------------------------
__global__ void __launch_bounds__(64, 8)
masif_k2b(const float* __restrict__ b2,
          const float* __restrict__ W3, const float* __restrict__ b3,
          float* __restrict__ out)
{
    __shared__ float s_h2[64];
    __shared__ float s_logit[NLL];
    const int tid = threadIdx.x;
    const int b = blockIdx.x;

    {
        float v = b2[tid];
#pragma unroll
        for (int s = 0; s < 8; ++s)
            v += g_p2[(b * 8 + s) * 64 + tid];
        s_h2[tid] = fmaxf(v, 0.0f);
    }
    __syncthreads();
    if (tid < NLL) {
        float s = b3[tid];
#pragma unroll
        for (int j = 0; j < 64; ++j)
            s = fmaf(s_h2[j], W3[j * NLL + tid], s);
        s_logit[tid] = s;
    }
    __syncthreads();
    if (tid == 0) {
        float m = -INFINITY;
        for (int l = 0; l < NLL; ++l) m = fmaxf(m, s_logit[l]);
        float e[NLL];
        float sum = 0.0f;
        for (int l = 0; l < NLL; ++l) { e[l] = __expf(s_logit[l] - m); sum += e[l]; }
        float inv = 1.0f / sum;
        for (int l = 0; l < NLL; ++l) out[b * NLL + l] = e[l] * inv;
    }
}

extern "C" void kernel_launch(void* const* d_in, const int* in_sizes, int n_in,
                              void* d_out, int out_size)
{
    const float* x           = (const float*)d_in[0];
    const float* mu_rho      = (const float*)d_in[1];
    const float* sigma_rho   = (const float*)d_in[2];
    const float* mu_theta    = (const float*)d_in[3];
    const float* sigma_theta = (const float*)d_in[4];
    const float* W_conv      = (const float*)d_in[5];
    const float* b_conv      = (const float*)d_in[6];
    const float* W1          = (const float*)d_in[7];
    const float* b1          = (const float*)d_in[8];
    const float* W2          = (const float*)d_in[9];
    const float* b2          = (const float*)d_in[10];
    const float* W3          = (const float*)d_in[11];
    const float* b3          = (const float*)d_in[12];
    float* out = (float*)d_out;

    masif_k1<<<BBATCH * PP, 256>>>(x, mu_rho, sigma_rho, mu_theta, sigma_theta,
                                   W_conv, b_conv, W1, b1);
    masif_k2a<<<dim3(8, BBATCH), 256>>>(W2);
    masif_k2b<<<BBATCH, 64>>>(b2, W3, b3, out);
}